// round 1
// baseline (speedup 1.0000x reference)
#include <cuda_runtime.h>
#include <math.h>
#include <stdint.h>

// Problem constants (DozerAttentionLayer): B=2, L=S=2048, D=1024, H=16, DK=64
#define B_   2
#define L_   2048
#define S_   2048
#define D_   1024
#define H_   16
#define DK_  64
#define NROW (B_ * L_)          // 4096 rows for all projections
#define NTILE_S (S_ / 64)       // 32 s-tiles

// ---------------------------------------------------------------------------
// Device-global scratch (allocation-free rule: static __device__ arrays)
// ---------------------------------------------------------------------------
__device__ float g_q [(size_t)B_ * H_ * L_ * DK_];   // [B,H,L,DK] 16MB
__device__ float g_k [(size_t)B_ * H_ * S_ * DK_];   // [B,H,S,DK] 16MB
__device__ float g_v [(size_t)B_ * H_ * S_ * DK_];   // [B,H,S,DK] 16MB
__device__ float g_ho[(size_t)B_ * L_ * H_ * DK_];   // [B,L,H*DK] 16MB
// Fallback scratch in case the harness output buffer only holds `out`
// (expected case: out buffer = out ++ attn, so this stays untouched BSS).
__device__ float g_attn_scratch[(size_t)B_ * H_ * L_ * S_];

// ---------------------------------------------------------------------------
// Fast exp: FMA-only (avoids the MUFU rt=8 bottleneck: 134M exps needed).
// exp(x) = 2^k * e^r, k = round(x*log2e), r = (x*log2e - k)*ln2, |r|<=0.347
// Degree-5 Taylor => rel err ~2.4e-6. Valid for x <= 0 (our only use).
// ---------------------------------------------------------------------------
__device__ __forceinline__ float fexp(float x) {
    x = fmaxf(x, -80.0f);                         // avoid denormal/garbage
    float t = x * 1.4426950408889634f;            // x * log2(e)
    float z = t + 12582912.0f;                    // round-to-nearest magic (1.5*2^23)
    int   k = __float_as_int(z) - 0x4b400000;     // = round(t)
    float f = t - (z - 12582912.0f);              // frac in [-0.5, 0.5]
    float r = f * 0.6931471805599453f;            // f * ln2
    float p = fmaf(r, 8.33333333e-3f, 4.16666667e-2f);
    p = fmaf(p, r, 1.66666667e-1f);
    p = fmaf(p, r, 0.5f);
    p = fmaf(p, r, 1.0f);
    p = fmaf(p, r, 1.0f);                         // e^r
    return __int_as_float(__float_as_int(p) + (k << 23));  // * 2^k
}

// ---------------------------------------------------------------------------
// Dense GEMM: Y[N,1024] = X[N,1024] @ W[1024,1024] + bias
// 64x64 block tile, 256 threads, 4x4 per thread, K-tile 16.
// headLayout=1 scatters output to [B, H, T, DK] (for Q/K/V); else row-major.
// ---------------------------------------------------------------------------
__global__ __launch_bounds__(256) void proj_kernel(
    const float* __restrict__ X, const float* __restrict__ W,
    const float* __restrict__ bias, float* __restrict__ out, int headLayout)
{
    __shared__ float Xs[64][17];
    __shared__ float Ws[16][68];

    const int tid = threadIdx.x;
    const int tx = tid & 15, ty = tid >> 4;
    const int row0 = blockIdx.y * 64;
    const int col0 = blockIdx.x * 64;

    float acc[4][4];
#pragma unroll
    for (int i = 0; i < 4; i++)
#pragma unroll
        for (int j = 0; j < 4; j++) acc[i][j] = 0.0f;

    for (int k0 = 0; k0 < D_; k0 += 16) {
        {   // X tile: 64 x 16
            int r = tid >> 2, c4 = tid & 3;
            float4 v = *reinterpret_cast<const float4*>(
                X + (size_t)(row0 + r) * D_ + k0 + c4 * 4);
            Xs[r][c4 * 4 + 0] = v.x; Xs[r][c4 * 4 + 1] = v.y;
            Xs[r][c4 * 4 + 2] = v.z; Xs[r][c4 * 4 + 3] = v.w;
        }
        {   // W tile: 16 x 64
            int kk = tid >> 4, c = tid & 15;
            float4 v = *reinterpret_cast<const float4*>(
                W + (size_t)(k0 + kk) * D_ + col0 + c * 4);
            *reinterpret_cast<float4*>(&Ws[kk][c * 4]) = v;
        }
        __syncthreads();
#pragma unroll
        for (int kk = 0; kk < 16; kk++) {
            float4 b4 = *reinterpret_cast<const float4*>(&Ws[kk][tx * 4]);
            float bv[4] = {b4.x, b4.y, b4.z, b4.w};
            float av[4];
#pragma unroll
            for (int i = 0; i < 4; i++) av[i] = Xs[ty * 4 + i][kk];
#pragma unroll
            for (int i = 0; i < 4; i++)
#pragma unroll
                for (int j = 0; j < 4; j++)
                    acc[i][j] = fmaf(av[i], bv[j], acc[i][j]);
        }
        __syncthreads();
    }

    // epilogue: + bias, write out
#pragma unroll
    for (int i = 0; i < 4; i++) {
        int row = row0 + ty * 4 + i;
        float4 v;
        v.x = acc[i][0] + bias[col0 + tx * 4 + 0];
        v.y = acc[i][1] + bias[col0 + tx * 4 + 1];
        v.z = acc[i][2] + bias[col0 + tx * 4 + 2];
        v.w = acc[i][3] + bias[col0 + tx * 4 + 3];
        if (headLayout) {
            int b = row >> 11;          // row / 2048
            int t = row & 2047;
            int h = col0 >> 6;          // one head per 64-col block
            *reinterpret_cast<float4*>(
                out + (((size_t)(b * H_ + h) * L_ + t) * DK_) + tx * 4) = v;
        } else {
            *reinterpret_cast<float4*>(
                out + (size_t)row * D_ + col0 + tx * 4) = v;
        }
    }
}

// ---------------------------------------------------------------------------
// Attention: per CTA = (64 query rows, one (b,h)).
// Phase 1: S-tiles of 64: scores = q k^T * scale (+mask), online max/sum,
//          write exp(s - m_tile) to attn buffer, record m_tile per row.
// Phase 2: re-read, rescale to final probabilities in place, accumulate P@V.
// ---------------------------------------------------------------------------
__global__ __launch_bounds__(256) void attn_kernel(
    const unsigned char* __restrict__ mask8, float* __restrict__ attn)
{
    __shared__ float bufA[64][68];   // phase1: q tile [l][dk]; phase2: v tile [s][dk]
    __shared__ float bufB[64][68];   // phase1: k^T tile [dk][s]; phase2: p tile [l][s]
    __shared__ float mw[64][NTILE_S];

    const int tid = threadIdx.x;
    const int tx = tid & 15, ty = tid >> 4;
    const int b = blockIdx.z, h = blockIdx.y;
    const int l0 = blockIdx.x * 64;
    const float scale = 0.125f;   // 1/sqrt(64)

    // auto-detect mask dtype (jax bool -> uint8 expected; int32 fallback)
    const bool maskInt = (mask8[0] != 0 && mask8[1] == 0 && mask8[2] == 0 && mask8[3] == 0);
    const int* mask32 = reinterpret_cast<const int*>(mask8);

    const float* qg = g_q + (size_t)(b * H_ + h) * L_ * DK_;
    const float* kg = g_k + (size_t)(b * H_ + h) * S_ * DK_;
    const float* vg = g_v + (size_t)(b * H_ + h) * S_ * DK_;
    float* ap = attn + ((size_t)(b * H_ + h) * L_ + l0) * S_;

    // load q tile
#pragma unroll
    for (int it = 0; it < 4; it++) {
        int idx = tid + it * 256;
        int r = idx >> 4, c = idx & 15;
        float4 v = *reinterpret_cast<const float4*>(qg + (size_t)(l0 + r) * DK_ + c * 4);
        *reinterpret_cast<float4*>(&bufA[r][c * 4]) = v;
    }

    float mrun[4], srun[4];
#pragma unroll
    for (int i = 0; i < 4; i++) { mrun[i] = -3.0e38f; srun[i] = 0.0f; }

    // ---------------- Phase 1 ----------------
    for (int st = 0; st < NTILE_S; st++) {
        int s0 = st * 64;
        // load k tile transposed: bufB[dk][s]
#pragma unroll
        for (int it = 0; it < 4; it++) {
            int idx = tid + it * 256;
            int r = idx >> 4, c = idx & 15;
            float4 v = *reinterpret_cast<const float4*>(kg + (size_t)(s0 + r) * DK_ + c * 4);
            bufB[c * 4 + 0][r] = v.x; bufB[c * 4 + 1][r] = v.y;
            bufB[c * 4 + 2][r] = v.z; bufB[c * 4 + 3][r] = v.w;
        }
        __syncthreads();

        float acc[4][4];
#pragma unroll
        for (int i = 0; i < 4; i++)
#pragma unroll
            for (int j = 0; j < 4; j++) acc[i][j] = 0.0f;

#pragma unroll 8
        for (int kk = 0; kk < 64; kk++) {
            float4 b4 = *reinterpret_cast<const float4*>(&bufB[kk][tx * 4]);
            float bv[4] = {b4.x, b4.y, b4.z, b4.w};
            float av[4];
#pragma unroll
            for (int i = 0; i < 4; i++) av[i] = bufA[ty * 4 + i][kk];
#pragma unroll
            for (int i = 0; i < 4; i++)
#pragma unroll
                for (int j = 0; j < 4; j++)
                    acc[i][j] = fmaf(av[i], bv[j], acc[i][j]);
        }

#pragma unroll
        for (int i = 0; i < 4; i++) {
            int l = l0 + ty * 4 + i;
            float sv[4];
            bool keep[4];
            if (maskInt) {
                int4 mv = *reinterpret_cast<const int4*>(mask32 + (size_t)l * S_ + s0 + tx * 4);
                keep[0] = mv.x != 0; keep[1] = mv.y != 0; keep[2] = mv.z != 0; keep[3] = mv.w != 0;
            } else {
                uchar4 mv = *reinterpret_cast<const uchar4*>(mask8 + (size_t)l * S_ + s0 + tx * 4);
                keep[0] = mv.x != 0; keep[1] = mv.y != 0; keep[2] = mv.z != 0; keep[3] = mv.w != 0;
            }
#pragma unroll
            for (int j = 0; j < 4; j++)
                sv[j] = keep[j] ? acc[i][j] * scale : -1.0e30f;

            float tm = fmaxf(fmaxf(sv[0], sv[1]), fmaxf(sv[2], sv[3]));
            tm = fmaxf(tm, __shfl_xor_sync(0xffffffff, tm, 1));
            tm = fmaxf(tm, __shfl_xor_sync(0xffffffff, tm, 2));
            tm = fmaxf(tm, __shfl_xor_sync(0xffffffff, tm, 4));
            tm = fmaxf(tm, __shfl_xor_sync(0xffffffff, tm, 8));
            float nm = fmaxf(mrun[i], tm);

            float e0 = fexp(sv[0] - nm), e1 = fexp(sv[1] - nm);
            float e2 = fexp(sv[2] - nm), e3 = fexp(sv[3] - nm);
            float ts = (e0 + e1) + (e2 + e3);
            ts += __shfl_xor_sync(0xffffffff, ts, 1);
            ts += __shfl_xor_sync(0xffffffff, ts, 2);
            ts += __shfl_xor_sync(0xffffffff, ts, 4);
            ts += __shfl_xor_sync(0xffffffff, ts, 8);

            srun[i] = srun[i] * fexp(mrun[i] - nm) + ts;
            mrun[i] = nm;

            float4 ev = make_float4(e0, e1, e2, e3);
            *reinterpret_cast<float4*>(ap + (size_t)(ty * 4 + i) * S_ + s0 + tx * 4) = ev;
            if (tx == 0) mw[ty * 4 + i][st] = nm;
        }
        __syncthreads();
    }

    float inv[4], mf[4];
#pragma unroll
    for (int i = 0; i < 4; i++) { inv[i] = 1.0f / srun[i]; mf[i] = mrun[i]; }

    // ---------------- Phase 2 ----------------
    float o[4][4];
#pragma unroll
    for (int i = 0; i < 4; i++)
#pragma unroll
        for (int j = 0; j < 4; j++) o[i][j] = 0.0f;

    for (int st = 0; st < NTILE_S; st++) {
        int s0 = st * 64;
        // v tile -> bufA [s][dk]
#pragma unroll
        for (int it = 0; it < 4; it++) {
            int idx = tid + it * 256;
            int r = idx >> 4, c = idx & 15;
            *reinterpret_cast<float4*>(&bufA[r][c * 4]) =
                *reinterpret_cast<const float4*>(vg + (size_t)(s0 + r) * DK_ + c * 4);
        }
        // p tile: rescale in place, store to bufB [l][s]
#pragma unroll
        for (int i = 0; i < 4; i++) {
            int li = ty * 4 + i;
            float sc = fexp(mw[li][st] - mf[i]) * inv[i];
            float4 e4 = *reinterpret_cast<const float4*>(ap + (size_t)li * S_ + s0 + tx * 4);
            float4 p4 = make_float4(e4.x * sc, e4.y * sc, e4.z * sc, e4.w * sc);
            *reinterpret_cast<float4*>(ap + (size_t)li * S_ + s0 + tx * 4) = p4;
            *reinterpret_cast<float4*>(&bufB[li][tx * 4]) = p4;
        }
        __syncthreads();

#pragma unroll 8
        for (int kk = 0; kk < 64; kk++) {
            float4 b4 = *reinterpret_cast<const float4*>(&bufA[kk][tx * 4]);
            float bv[4] = {b4.x, b4.y, b4.z, b4.w};
            float av[4];
#pragma unroll
            for (int i = 0; i < 4; i++) av[i] = bufB[ty * 4 + i][kk];
#pragma unroll
            for (int i = 0; i < 4; i++)
#pragma unroll
                for (int j = 0; j < 4; j++)
                    o[i][j] = fmaf(av[i], bv[j], o[i][j]);
        }
        __syncthreads();
    }

    // write head outputs -> g_ho [B, L, H*DK]
#pragma unroll
    for (int i = 0; i < 4; i++) {
        int l = l0 + ty * 4 + i;
        *reinterpret_cast<float4*>(
            g_ho + ((size_t)(b * L_ + l) * H_ + h) * DK_ + tx * 4) =
            make_float4(o[i][0], o[i][1], o[i][2], o[i][3]);
    }
}

// ---------------------------------------------------------------------------
// kernel_launch
// Inputs (metadata order): queries, keys, values, attn_mask,
//                          Wq, bq, Wk, bk, Wv, bv, Wo, bo
// Output: out [B,L,D] followed by attn [B,H,L,S] (tuple concat)
// ---------------------------------------------------------------------------
extern "C" void kernel_launch(void* const* d_in, const int* in_sizes, int n_in,
                              void* d_out, int out_size)
{
    const float* queries = (const float*)d_in[0];
    const float* keys    = (const float*)d_in[1];
    const float* values  = (const float*)d_in[2];
    const unsigned char* mask = (const unsigned char*)d_in[3];
    const float* Wq = (const float*)d_in[4];
    const float* bq = (const float*)d_in[5];
    const float* Wk = (const float*)d_in[6];
    const float* bk = (const float*)d_in[7];
    const float* Wv = (const float*)d_in[8];
    const float* bv = (const float*)d_in[9];
    const float* Wo = (const float*)d_in[10];
    const float* bo = (const float*)d_in[11];

    float* out = (float*)d_out;
    const size_t OUT_ELEMS  = (size_t)B_ * L_ * D_;
    const size_t ATTN_ELEMS = (size_t)B_ * H_ * L_ * S_;

    float *pq, *pk, *pv, *pho, *pattn_scratch;
    cudaGetSymbolAddress((void**)&pq,  g_q);
    cudaGetSymbolAddress((void**)&pk,  g_k);
    cudaGetSymbolAddress((void**)&pv,  g_v);
    cudaGetSymbolAddress((void**)&pho, g_ho);
    cudaGetSymbolAddress((void**)&pattn_scratch, g_attn_scratch);

    // attn matrix destination: second tuple element in d_out if it fits,
    // else device scratch (attn then not an output).
    float* attn = ((size_t)out_size >= OUT_ELEMS + ATTN_ELEMS)
                      ? (out + OUT_ELEMS) : pattn_scratch;

    dim3 gp(D_ / 64, NROW / 64);   // (16, 64)
    proj_kernel<<<gp, 256>>>(queries, Wq, bq, pq, 1);
    proj_kernel<<<gp, 256>>>(keys,    Wk, bk, pk, 1);
    proj_kernel<<<gp, 256>>>(values,  Wv, bv, pv, 1);

    dim3 ga(L_ / 64, H_, B_);      // (32, 16, 2)
    attn_kernel<<<ga, 256>>>(mask, attn);

    proj_kernel<<<gp, 256>>>(pho, Wo, bo, out, 0);
}

// round 3
// speedup vs baseline: 1.3101x; 1.3101x over previous
#include <cuda_runtime.h>
#include <cuda_bf16.h>
#include <math.h>
#include <stdint.h>

// Problem constants (DozerAttentionLayer): B=2, L=S=2048, D=1024, H=16, DK=64
#define B_   2
#define L_   2048
#define S_   2048
#define D_   1024
#define H_   16
#define DK_  64
#define NROW (B_ * L_)          // 4096 rows for all projections
#define NTILE_S (S_ / 64)       // 32 s-tiles

// ---------------------------------------------------------------------------
// Device-global scratch (allocation-free rule: static __device__ arrays)
// ---------------------------------------------------------------------------
__device__ float g_q [(size_t)B_ * H_ * L_ * DK_];   // [B,H,L,DK]
__device__ float g_k [(size_t)B_ * H_ * S_ * DK_];
__device__ float g_v [(size_t)B_ * H_ * S_ * DK_];
__device__ float g_ho[(size_t)B_ * L_ * H_ * DK_];   // [B,L,H*DK]
__device__ float g_attn_scratch[(size_t)B_ * H_ * L_ * S_];
// bf16 hi/lo split scratch for tensor-core projections
__device__ __nv_bfloat16 g_xhi[(size_t)NROW * D_];
__device__ __nv_bfloat16 g_xlo[(size_t)NROW * D_];
__device__ __nv_bfloat16 g_whi[(size_t)D_ * D_];     // W^T  [n][k]
__device__ __nv_bfloat16 g_wlo[(size_t)D_ * D_];

// ---------------------------------------------------------------------------
// Tensor-core helpers (sm_80-era PTX: legal on plain sm_103 target)
// ---------------------------------------------------------------------------
__device__ __forceinline__ uint32_t smem_u32(const void* p) {
    uint32_t a;
    asm("{ .reg .u64 t; cvta.to.shared.u64 t, %1; cvt.u32.u64 %0, t; }"
        : "=r"(a) : "l"(p));
    return a;
}
__device__ __forceinline__ void ldsm4(uint32_t& r0, uint32_t& r1,
                                      uint32_t& r2, uint32_t& r3, uint32_t addr) {
    asm volatile("ldmatrix.sync.aligned.m8n8.x4.shared.b16 {%0,%1,%2,%3}, [%4];"
        : "=r"(r0), "=r"(r1), "=r"(r2), "=r"(r3) : "r"(addr));
}
__device__ __forceinline__ void mma16816(float* c, const uint32_t* a,
                                         uint32_t b0, uint32_t b1) {
    asm volatile("mma.sync.aligned.m16n8k16.row.col.f32.bf16.bf16.f32 "
        "{%0,%1,%2,%3}, {%4,%5,%6,%7}, {%8,%9}, {%0,%1,%2,%3};"
        : "+f"(c[0]), "+f"(c[1]), "+f"(c[2]), "+f"(c[3])
        : "r"(a[0]), "r"(a[1]), "r"(a[2]), "r"(a[3]), "r"(b0), "r"(b1));
}

// ---------------------------------------------------------------------------
// Fast exp: FMA-only. Valid for x <= 0 (our only use). rel err ~2.4e-6.
// ---------------------------------------------------------------------------
__device__ __forceinline__ float fexp(float x) {
    x = fmaxf(x, -80.0f);
    float t = x * 1.4426950408889634f;
    float z = t + 12582912.0f;
    int   k = __float_as_int(z) - 0x4b400000;
    float f = t - (z - 12582912.0f);
    float r = f * 0.6931471805599453f;
    float p = fmaf(r, 8.33333333e-3f, 4.16666667e-2f);
    p = fmaf(p, r, 1.66666667e-1f);
    p = fmaf(p, r, 0.5f);
    p = fmaf(p, r, 1.0f);
    p = fmaf(p, r, 1.0f);
    return __int_as_float(__float_as_int(p) + (k << 23));
}

// ---------------------------------------------------------------------------
// hi/lo bf16 split of a fp32 matrix (elementwise, vectorized by 4)
// ---------------------------------------------------------------------------
__global__ __launch_bounds__(256) void convert_hilo(
    const float4* __restrict__ x, __nv_bfloat16* __restrict__ hi,
    __nv_bfloat16* __restrict__ lo, int n4)
{
    int i = blockIdx.x * blockDim.x + threadIdx.x;
    if (i >= n4) return;
    float4 v = x[i];
    __nv_bfloat16 h0 = __float2bfloat16(v.x), h1 = __float2bfloat16(v.y);
    __nv_bfloat16 h2 = __float2bfloat16(v.z), h3 = __float2bfloat16(v.w);
    __nv_bfloat162* hp = reinterpret_cast<__nv_bfloat162*>(hi);
    __nv_bfloat162* lp = reinterpret_cast<__nv_bfloat162*>(lo);
    hp[2 * i]     = __nv_bfloat162(h0, h1);
    hp[2 * i + 1] = __nv_bfloat162(h2, h3);
    lp[2 * i]     = __nv_bfloat162(__float2bfloat16(v.x - __bfloat162float(h0)),
                                   __float2bfloat16(v.y - __bfloat162float(h1)));
    lp[2 * i + 1] = __nv_bfloat162(__float2bfloat16(v.z - __bfloat162float(h2)),
                                   __float2bfloat16(v.w - __bfloat162float(h3)));
}

// ---------------------------------------------------------------------------
// W [1024k][1024n] fp32 -> W^T hi/lo bf16 [1024n][1024k]
// ---------------------------------------------------------------------------
__global__ __launch_bounds__(256) void convert_w_t(
    const float* __restrict__ W, __nv_bfloat16* __restrict__ whi,
    __nv_bfloat16* __restrict__ wlo)
{
    __shared__ float ts[32][33];
    int n0 = blockIdx.x * 32, k0 = blockIdx.y * 32;
    int lx = threadIdx.x & 31, ly = threadIdx.x >> 5;   // ly 0..7
#pragma unroll
    for (int i = 0; i < 4; i++) {
        int r = ly + i * 8;
        ts[r][lx] = W[(size_t)(k0 + r) * D_ + n0 + lx];
    }
    __syncthreads();
#pragma unroll
    for (int i = 0; i < 4; i++) {
        int ln = ly + i * 8;
        float v = ts[lx][ln];
        __nv_bfloat16 h = __float2bfloat16(v);
        whi[(size_t)(n0 + ln) * D_ + k0 + lx] = h;
        wlo[(size_t)(n0 + ln) * D_ + k0 + lx] = __float2bfloat16(v - __bfloat162float(h));
    }
}

// ---------------------------------------------------------------------------
// bf16x3 projection GEMM on mma.sync: C[4096 x 1024] = X @ W + bias
// X hi/lo bf16 [row][k]; W^T hi/lo bf16 [n][k].
// CTA 128x128, 8 warps (2m x 4n), warp tile 64x32, K-tile 32, double buffer.
// C = Xhi*Whi + Xhi*Wlo + Xlo*Whi  (3 mma passes, shared accumulators).
// ---------------------------------------------------------------------------
#define PITCH 80                 // smem bytes per row (32 bf16 + 8 pad)
#define TILE_B (128 * PITCH)     // 10240 bytes per sub-tile
#define OFF_AHI 0
#define OFF_ALO (TILE_B)
#define OFF_BHI (2 * TILE_B)
#define OFF_BLO (3 * TILE_B)
#define STAGE_B (4 * TILE_B)     // 40960
#define PROJ_SMEM (2 * STAGE_B)  // 81920
#define NKT (D_ / 32)            // 32 k-tiles

__global__ __launch_bounds__(256) void proj_mma_kernel(
    const __nv_bfloat16* __restrict__ Xhi, const __nv_bfloat16* __restrict__ Xlo,
    const __nv_bfloat16* __restrict__ Whi, const __nv_bfloat16* __restrict__ Wlo,
    const float* __restrict__ bias, float* __restrict__ out, int headLayout)
{
    extern __shared__ char smem[];
    const uint32_t sb = smem_u32(smem);
    const int tid = threadIdx.x, wid = tid >> 5, lane = tid & 31;
    const int wm = wid >> 2, wn = wid & 3;          // warp 64-row, 32-col offset
    const int m0 = blockIdx.y * 128, n0 = blockIdx.x * 128;

    const uint4* gXhi = reinterpret_cast<const uint4*>(Xhi);
    const uint4* gXlo = reinterpret_cast<const uint4*>(Xlo);
    const uint4* gWhi = reinterpret_cast<const uint4*>(Whi);
    const uint4* gWlo = reinterpret_cast<const uint4*>(Wlo);

    float acc[4][4][4];
#pragma unroll
    for (int i = 0; i < 4; i++)
#pragma unroll
        for (int j = 0; j < 4; j++)
#pragma unroll
            for (int r = 0; r < 4; r++) acc[i][j][r] = 0.0f;

    // per-thread load coords: 512 uint4 per sub-tile, 2 per thread
    const int ldr0 = tid >> 2, ldc = tid & 3;       // r: tid/4, +64 for i=1

    // ---- prologue: stage 0 ----
    {
#pragma unroll
        for (int i = 0; i < 2; i++) {
            int r = ldr0 + i * 64;
            size_t ga = (size_t)(m0 + r) * (D_ / 8) + ldc;
            size_t gb = (size_t)(n0 + r) * (D_ / 8) + ldc;
            uint32_t off = (uint32_t)(r * PITCH + ldc * 16);
            *reinterpret_cast<uint4*>(smem + OFF_AHI + off) = gXhi[ga];
            *reinterpret_cast<uint4*>(smem + OFF_ALO + off) = gXlo[ga];
            *reinterpret_cast<uint4*>(smem + OFF_BHI + off) = gWhi[gb];
            *reinterpret_cast<uint4*>(smem + OFF_BLO + off) = gWlo[gb];
        }
    }
    __syncthreads();

    // ldmatrix lane addressing
    const int lrow = (lane & 7) + ((lane >> 3) & 1) * 8;   // row within 16
    const int lkb  = (lane >> 4) * 16;                     // k-byte half

    for (int kt = 0; kt < NKT; kt++) {
        const int buf = kt & 1;
        const bool pre = (kt + 1 < NKT);
        uint4 st[8];
        if (pre) {
            const int kq = (kt + 1) * 4;
#pragma unroll
            for (int i = 0; i < 2; i++) {
                int r = ldr0 + i * 64;
                size_t ga = (size_t)(m0 + r) * (D_ / 8) + kq + ldc;
                size_t gb = (size_t)(n0 + r) * (D_ / 8) + kq + ldc;
                st[i]     = gXhi[ga];
                st[2 + i] = gXlo[ga];
                st[4 + i] = gWhi[gb];
                st[6 + i] = gWlo[gb];
            }
        }

        // ---- compute on buf ----
        const uint32_t sbase = sb + buf * STAGE_B;
#pragma unroll
        for (int k16 = 0; k16 < 2; k16++) {
            const uint32_t kOff = k16 * 32 + lkb;
            uint32_t ahi[4][4], alo[4][4], bhi[2][4], blo[2][4];
#pragma unroll
            for (int im = 0; im < 4; im++) {
                uint32_t row = wm * 64 + im * 16 + lrow;
                uint32_t ad = sbase + row * PITCH + kOff;
                ldsm4(ahi[im][0], ahi[im][1], ahi[im][2], ahi[im][3], ad + OFF_AHI);
                ldsm4(alo[im][0], alo[im][1], alo[im][2], alo[im][3], ad + OFF_ALO);
            }
#pragma unroll
            for (int is = 0; is < 2; is++) {
                uint32_t nrow = wn * 32 + is * 16 + lrow;
                uint32_t bd = sbase + nrow * PITCH + kOff;
                ldsm4(bhi[is][0], bhi[is][1], bhi[is][2], bhi[is][3], bd + OFF_BHI);
                ldsm4(blo[is][0], blo[is][1], blo[is][2], blo[is][3], bd + OFF_BLO);
            }
#pragma unroll
            for (int im = 0; im < 4; im++)
#pragma unroll
                for (int is = 0; is < 2; is++)
#pragma unroll
                    for (int nn = 0; nn < 2; nn++) {
                        float* c = acc[im][is * 2 + nn];
                        mma16816(c, ahi[im], bhi[is][nn], bhi[is][nn + 2]);
                        mma16816(c, ahi[im], blo[is][nn], blo[is][nn + 2]);
                        mma16816(c, alo[im], bhi[is][nn], bhi[is][nn + 2]);
                    }
        }

        if (pre) {
            char* dst = smem + ((kt + 1) & 1) * STAGE_B;
#pragma unroll
            for (int i = 0; i < 2; i++) {
                int r = ldr0 + i * 64;
                uint32_t off = (uint32_t)(r * PITCH + ldc * 16);
                *reinterpret_cast<uint4*>(dst + OFF_AHI + off) = st[i];
                *reinterpret_cast<uint4*>(dst + OFF_ALO + off) = st[2 + i];
                *reinterpret_cast<uint4*>(dst + OFF_BHI + off) = st[4 + i];
                *reinterpret_cast<uint4*>(dst + OFF_BLO + off) = st[6 + i];
            }
        }
        __syncthreads();
    }

    // ---- epilogue ----
    const int qr = lane >> 2, qc = lane & 3;
#pragma unroll
    for (int im = 0; im < 4; im++) {
#pragma unroll
        for (int in = 0; in < 4; in++) {
            int col = n0 + wn * 32 + in * 8 + qc * 2;
            float bx = bias[col], by = bias[col + 1];
#pragma unroll
            for (int half = 0; half < 2; half++) {
                int row = m0 + wm * 64 + im * 16 + qr + half * 8;
                float2 v;
                v.x = acc[im][in][half * 2 + 0] + bx;
                v.y = acc[im][in][half * 2 + 1] + by;
                if (headLayout) {
                    int bI = row >> 11, tI = row & 2047;
                    int h = col >> 6, cc = col & 63;
                    *reinterpret_cast<float2*>(
                        out + (((size_t)(bI * H_ + h) * L_ + tI) << 6) + cc) = v;
                } else {
                    *reinterpret_cast<float2*>(out + (size_t)row * D_ + col) = v;
                }
            }
        }
    }
}

// ---------------------------------------------------------------------------
// Attention (round-1 fp32 version — known good; next round's target)
// ---------------------------------------------------------------------------
__global__ __launch_bounds__(256) void attn_kernel(
    const unsigned char* __restrict__ mask8, float* __restrict__ attn)
{
    __shared__ float bufA[64][68];
    __shared__ float bufB[64][68];
    __shared__ float mw[64][NTILE_S];

    const int tid = threadIdx.x;
    const int tx = tid & 15, ty = tid >> 4;
    const int b = blockIdx.z, h = blockIdx.y;
    const int l0 = blockIdx.x * 64;
    const float scale = 0.125f;

    const bool maskInt = (mask8[0] != 0 && mask8[1] == 0 && mask8[2] == 0 && mask8[3] == 0);
    const int* mask32 = reinterpret_cast<const int*>(mask8);

    const float* qg = g_q + (size_t)(b * H_ + h) * L_ * DK_;
    const float* kg = g_k + (size_t)(b * H_ + h) * S_ * DK_;
    const float* vg = g_v + (size_t)(b * H_ + h) * S_ * DK_;
    float* ap = attn + ((size_t)(b * H_ + h) * L_ + l0) * S_;

#pragma unroll
    for (int it = 0; it < 4; it++) {
        int idx = tid + it * 256;
        int r = idx >> 4, c = idx & 15;
        float4 v = *reinterpret_cast<const float4*>(qg + (size_t)(l0 + r) * DK_ + c * 4);
        *reinterpret_cast<float4*>(&bufA[r][c * 4]) = v;
    }

    float mrun[4], srun[4];
#pragma unroll
    for (int i = 0; i < 4; i++) { mrun[i] = -3.0e38f; srun[i] = 0.0f; }

    for (int st = 0; st < NTILE_S; st++) {
        int s0 = st * 64;
#pragma unroll
        for (int it = 0; it < 4; it++) {
            int idx = tid + it * 256;
            int r = idx >> 4, c = idx & 15;
            float4 v = *reinterpret_cast<const float4*>(kg + (size_t)(s0 + r) * DK_ + c * 4);
            bufB[c * 4 + 0][r] = v.x; bufB[c * 4 + 1][r] = v.y;
            bufB[c * 4 + 2][r] = v.z; bufB[c * 4 + 3][r] = v.w;
        }
        __syncthreads();

        float acc[4][4];
#pragma unroll
        for (int i = 0; i < 4; i++)
#pragma unroll
            for (int j = 0; j < 4; j++) acc[i][j] = 0.0f;

#pragma unroll 8
        for (int kk = 0; kk < 64; kk++) {
            float4 b4 = *reinterpret_cast<const float4*>(&bufB[kk][tx * 4]);
            float bv[4] = {b4.x, b4.y, b4.z, b4.w};
            float av[4];
#pragma unroll
            for (int i = 0; i < 4; i++) av[i] = bufA[ty * 4 + i][kk];
#pragma unroll
            for (int i = 0; i < 4; i++)
#pragma unroll
                for (int j = 0; j < 4; j++)
                    acc[i][j] = fmaf(av[i], bv[j], acc[i][j]);
        }

#pragma unroll
        for (int i = 0; i < 4; i++) {
            int l = l0 + ty * 4 + i;
            float sv[4];
            bool keep[4];
            if (maskInt) {
                int4 mv = *reinterpret_cast<const int4*>(mask32 + (size_t)l * S_ + s0 + tx * 4);
                keep[0] = mv.x != 0; keep[1] = mv.y != 0; keep[2] = mv.z != 0; keep[3] = mv.w != 0;
            } else {
                uchar4 mv = *reinterpret_cast<const uchar4*>(mask8 + (size_t)l * S_ + s0 + tx * 4);
                keep[0] = mv.x != 0; keep[1] = mv.y != 0; keep[2] = mv.z != 0; keep[3] = mv.w != 0;
            }
#pragma unroll
            for (int j = 0; j < 4; j++)
                sv[j] = keep[j] ? acc[i][j] * scale : -1.0e30f;

            float tm = fmaxf(fmaxf(sv[0], sv[1]), fmaxf(sv[2], sv[3]));
            tm = fmaxf(tm, __shfl_xor_sync(0xffffffff, tm, 1));
            tm = fmaxf(tm, __shfl_xor_sync(0xffffffff, tm, 2));
            tm = fmaxf(tm, __shfl_xor_sync(0xffffffff, tm, 4));
            tm = fmaxf(tm, __shfl_xor_sync(0xffffffff, tm, 8));
            float nm = fmaxf(mrun[i], tm);

            float e0 = fexp(sv[0] - nm), e1 = fexp(sv[1] - nm);
            float e2 = fexp(sv[2] - nm), e3 = fexp(sv[3] - nm);
            float ts = (e0 + e1) + (e2 + e3);
            ts += __shfl_xor_sync(0xffffffff, ts, 1);
            ts += __shfl_xor_sync(0xffffffff, ts, 2);
            ts += __shfl_xor_sync(0xffffffff, ts, 4);
            ts += __shfl_xor_sync(0xffffffff, ts, 8);

            srun[i] = srun[i] * fexp(mrun[i] - nm) + ts;
            mrun[i] = nm;

            *reinterpret_cast<float4*>(ap + (size_t)(ty * 4 + i) * S_ + s0 + tx * 4) =
                make_float4(e0, e1, e2, e3);
            if (tx == 0) mw[ty * 4 + i][st] = nm;
        }
        __syncthreads();
    }

    float inv[4], mf[4];
#pragma unroll
    for (int i = 0; i < 4; i++) { inv[i] = 1.0f / srun[i]; mf[i] = mrun[i]; }

    float o[4][4];
#pragma unroll
    for (int i = 0; i < 4; i++)
#pragma unroll
        for (int j = 0; j < 4; j++) o[i][j] = 0.0f;

    for (int st = 0; st < NTILE_S; st++) {
        int s0 = st * 64;
#pragma unroll
        for (int it = 0; it < 4; it++) {
            int idx = tid + it * 256;
            int r = idx >> 4, c = idx & 15;
            *reinterpret_cast<float4*>(&bufA[r][c * 4]) =
                *reinterpret_cast<const float4*>(vg + (size_t)(s0 + r) * DK_ + c * 4);
        }
#pragma unroll
        for (int i = 0; i < 4; i++) {
            int li = ty * 4 + i;
            float sc = fexp(mw[li][st] - mf[i]) * inv[i];
            float4 e4 = *reinterpret_cast<const float4*>(ap + (size_t)li * S_ + s0 + tx * 4);
            float4 p4 = make_float4(e4.x * sc, e4.y * sc, e4.z * sc, e4.w * sc);
            *reinterpret_cast<float4*>(ap + (size_t)li * S_ + s0 + tx * 4) = p4;
            *reinterpret_cast<float4*>(&bufB[li][tx * 4]) = p4;
        }
        __syncthreads();

#pragma unroll 8
        for (int kk = 0; kk < 64; kk++) {
            float4 b4 = *reinterpret_cast<const float4*>(&bufA[kk][tx * 4]);
            float bv[4] = {b4.x, b4.y, b4.z, b4.w};
            float av[4];
#pragma unroll
            for (int i = 0; i < 4; i++) av[i] = bufB[ty * 4 + i][kk];
#pragma unroll
            for (int i = 0; i < 4; i++)
#pragma unroll
                for (int j = 0; j < 4; j++)
                    o[i][j] = fmaf(av[i], bv[j], o[i][j]);
        }
        __syncthreads();
    }

#pragma unroll
    for (int i = 0; i < 4; i++) {
        int l = l0 + ty * 4 + i;
        *reinterpret_cast<float4*>(
            g_ho + ((size_t)(b * L_ + l) * H_ + h) * DK_ + tx * 4) =
            make_float4(o[i][0], o[i][1], o[i][2], o[i][3]);
    }
}

// ---------------------------------------------------------------------------
// kernel_launch
// ---------------------------------------------------------------------------
extern "C" void kernel_launch(void* const* d_in, const int* in_sizes, int n_in,
                              void* d_out, int out_size)
{
    const float* queries = (const float*)d_in[0];
    const float* keys    = (const float*)d_in[1];
    const float* values  = (const float*)d_in[2];
    const unsigned char* mask = (const unsigned char*)d_in[3];
    const float* Wq = (const float*)d_in[4];
    const float* bq = (const float*)d_in[5];
    const float* Wk = (const float*)d_in[6];
    const float* bk = (const float*)d_in[7];
    const float* Wv = (const float*)d_in[8];
    const float* bv = (const float*)d_in[9];
    const float* Wo = (const float*)d_in[10];
    const float* bo = (const float*)d_in[11];

    float* out = (float*)d_out;
    const size_t OUT_ELEMS  = (size_t)B_ * L_ * D_;
    const size_t ATTN_ELEMS = (size_t)B_ * H_ * L_ * S_;

    float *pq, *pk, *pv, *pho, *pattn_scratch;
    __nv_bfloat16 *pxhi, *pxlo, *pwhi, *pwlo;
    cudaGetSymbolAddress((void**)&pq,  g_q);
    cudaGetSymbolAddress((void**)&pk,  g_k);
    cudaGetSymbolAddress((void**)&pv,  g_v);
    cudaGetSymbolAddress((void**)&pho, g_ho);
    cudaGetSymbolAddress((void**)&pattn_scratch, g_attn_scratch);
    cudaGetSymbolAddress((void**)&pxhi, g_xhi);
    cudaGetSymbolAddress((void**)&pxlo, g_xlo);
    cudaGetSymbolAddress((void**)&pwhi, g_whi);
    cudaGetSymbolAddress((void**)&pwlo, g_wlo);

    float* attn = ((size_t)out_size >= OUT_ELEMS + ATTN_ELEMS)
                      ? (out + OUT_ELEMS) : pattn_scratch;

    static int smemSet = 0;
    if (!smemSet) {
        cudaFuncSetAttribute(proj_mma_kernel,
                             cudaFuncAttributeMaxDynamicSharedMemorySize, PROJ_SMEM);
        smemSet = 1;
    }

    const int n4 = NROW * D_ / 4;
    const dim3 gproj(D_ / 128, NROW / 128);   // (8, 32)
    const dim3 gw(D_ / 32, D_ / 32);          // (32, 32)

    // Q projection
    convert_hilo<<<n4 / 256, 256>>>((const float4*)queries, pxhi, pxlo, n4);
    convert_w_t<<<gw, 256>>>(Wq, pwhi, pwlo);
    proj_mma_kernel<<<gproj, 256, PROJ_SMEM>>>(pxhi, pxlo, pwhi, pwlo, bq, pq, 1);
    // K projection
    convert_hilo<<<n4 / 256, 256>>>((const float4*)keys, pxhi, pxlo, n4);
    convert_w_t<<<gw, 256>>>(Wk, pwhi, pwlo);
    proj_mma_kernel<<<gproj, 256, PROJ_SMEM>>>(pxhi, pxlo, pwhi, pwlo, bk, pk, 1);
    // V projection
    convert_hilo<<<n4 / 256, 256>>>((const float4*)values, pxhi, pxlo, n4);
    convert_w_t<<<gw, 256>>>(Wv, pwhi, pwlo);
    proj_mma_kernel<<<gproj, 256, PROJ_SMEM>>>(pxhi, pxlo, pwhi, pwlo, bv, pv, 1);

    // attention
    dim3 ga(L_ / 64, H_, B_);
    attn_kernel<<<ga, 256>>>(mask, attn);

    // output projection
    convert_hilo<<<n4 / 256, 256>>>((const float4*)pho, pxhi, pxlo, n4);
    convert_w_t<<<gw, 256>>>(Wo, pwhi, pwlo);
    proj_mma_kernel<<<gproj, 256, PROJ_SMEM>>>(pxhi, pxlo, pwhi, pwlo, bo, out, 0);
}

// round 5
// speedup vs baseline: 1.5767x; 1.2035x over previous
#include <cuda_runtime.h>
#include <cuda_bf16.h>
#include <math.h>
#include <stdint.h>

// Problem constants (DozerAttentionLayer): B=2, L=S=2048, D=1024, H=16, DK=64
#define B_   2
#define L_   2048
#define S_   2048
#define D_   1024
#define H_   16
#define DK_  64
#define NROW (B_ * L_)          // 4096 rows for all projections

// ---------------------------------------------------------------------------
// Device-global scratch
// ---------------------------------------------------------------------------
__device__ float g_attn_scratch[(size_t)B_ * H_ * L_ * S_];
// q/k/v hi-lo bf16, [B,H,T,DK]
__device__ __nv_bfloat16 g_qhi[(size_t)B_ * H_ * L_ * DK_];
__device__ __nv_bfloat16 g_qlo[(size_t)B_ * H_ * L_ * DK_];
__device__ __nv_bfloat16 g_khi[(size_t)B_ * H_ * S_ * DK_];
__device__ __nv_bfloat16 g_klo[(size_t)B_ * H_ * S_ * DK_];
__device__ __nv_bfloat16 g_vhi[(size_t)B_ * H_ * S_ * DK_];
__device__ __nv_bfloat16 g_vlo[(size_t)B_ * H_ * S_ * DK_];
// A-operand staging (inputs, and attn head-output) hi/lo
__device__ __nv_bfloat16 g_xhi[(size_t)NROW * D_];
__device__ __nv_bfloat16 g_xlo[(size_t)NROW * D_];
__device__ __nv_bfloat16 g_whi[(size_t)D_ * D_];     // W^T  [n][k]
__device__ __nv_bfloat16 g_wlo[(size_t)D_ * D_];
__device__ int g_maskflag[256];                      // per 128x128 tile: 1 = all true

// ---------------------------------------------------------------------------
// PTX helpers (sm_80-era: legal on plain sm_103 target)
// ---------------------------------------------------------------------------
__device__ __forceinline__ uint32_t smem_u32(const void* p) {
    uint32_t a;
    asm("{ .reg .u64 t; cvta.to.shared.u64 t, %1; cvt.u32.u64 %0, t; }"
        : "=r"(a) : "l"(p));
    return a;
}
__device__ __forceinline__ void ldsm4(uint32_t& r0, uint32_t& r1,
                                      uint32_t& r2, uint32_t& r3, uint32_t addr) {
    asm volatile("ldmatrix.sync.aligned.m8n8.x4.shared.b16 {%0,%1,%2,%3}, [%4];"
        : "=r"(r0), "=r"(r1), "=r"(r2), "=r"(r3) : "r"(addr));
}
__device__ __forceinline__ void ldsm4t(uint32_t& r0, uint32_t& r1,
                                       uint32_t& r2, uint32_t& r3, uint32_t addr) {
    asm volatile("ldmatrix.sync.aligned.m8n8.x4.trans.shared.b16 {%0,%1,%2,%3}, [%4];"
        : "=r"(r0), "=r"(r1), "=r"(r2), "=r"(r3) : "r"(addr));
}
__device__ __forceinline__ void mma16816(float* c, const uint32_t* a,
                                         uint32_t b0, uint32_t b1) {
    asm volatile("mma.sync.aligned.m16n8k16.row.col.f32.bf16.bf16.f32 "
        "{%0,%1,%2,%3}, {%4,%5,%6,%7}, {%8,%9}, {%0,%1,%2,%3};"
        : "+f"(c[0]), "+f"(c[1]), "+f"(c[2]), "+f"(c[3])
        : "r"(a[0]), "r"(a[1]), "r"(a[2]), "r"(a[3]), "r"(b0), "r"(b1));
}
__device__ __forceinline__ void cp16(uint32_t saddr, const void* g) {
    asm volatile("cp.async.cg.shared.global [%0], [%1], 16;"
        :: "r"(saddr), "l"(g) : "memory");
}
#define CP_COMMIT() asm volatile("cp.async.commit_group;" ::: "memory")
#define CP_WAIT(n)  asm volatile("cp.async.wait_group %0;" :: "n"(n) : "memory")

// pack two fp32 -> bf16x2 (lo in low half)
__device__ __forceinline__ uint32_t pack_bf2(float lo, float hi) {
    uint32_t r;
    asm("cvt.rn.bf16x2.f32 %0, %1, %2;" : "=r"(r) : "f"(hi), "f"(lo));
    return r;
}

// ---------------------------------------------------------------------------
// Fast exp: FMA-only. Valid for x <= 0. rel err ~2.4e-6.
// ---------------------------------------------------------------------------
__device__ __forceinline__ float fexp(float x) {
    x = fmaxf(x, -80.0f);
    float t = x * 1.4426950408889634f;
    float z = t + 12582912.0f;
    int   k = __float_as_int(z) - 0x4b400000;
    float f = t - (z - 12582912.0f);
    float r = f * 0.6931471805599453f;
    float p = fmaf(r, 8.33333333e-3f, 4.16666667e-2f);
    p = fmaf(p, r, 1.66666667e-1f);
    p = fmaf(p, r, 0.5f);
    p = fmaf(p, r, 1.0f);
    p = fmaf(p, r, 1.0f);
    return __int_as_float(__float_as_int(p) + (k << 23));
}

// ---------------------------------------------------------------------------
// hi/lo bf16 split of a fp32 matrix
// ---------------------------------------------------------------------------
__global__ __launch_bounds__(256) void convert_hilo(
    const float4* __restrict__ x, __nv_bfloat16* __restrict__ hi,
    __nv_bfloat16* __restrict__ lo, int n4)
{
    int i = blockIdx.x * blockDim.x + threadIdx.x;
    if (i >= n4) return;
    float4 v = x[i];
    __nv_bfloat16 h0 = __float2bfloat16(v.x), h1 = __float2bfloat16(v.y);
    __nv_bfloat16 h2 = __float2bfloat16(v.z), h3 = __float2bfloat16(v.w);
    __nv_bfloat162* hp = reinterpret_cast<__nv_bfloat162*>(hi);
    __nv_bfloat162* lp = reinterpret_cast<__nv_bfloat162*>(lo);
    hp[2 * i]     = __nv_bfloat162(h0, h1);
    hp[2 * i + 1] = __nv_bfloat162(h2, h3);
    lp[2 * i]     = __nv_bfloat162(__float2bfloat16(v.x - __bfloat162float(h0)),
                                   __float2bfloat16(v.y - __bfloat162float(h1)));
    lp[2 * i + 1] = __nv_bfloat162(__float2bfloat16(v.z - __bfloat162float(h2)),
                                   __float2bfloat16(v.w - __bfloat162float(h3)));
}

// W [1024k][1024n] fp32 -> W^T hi/lo bf16 [1024n][1024k]
__global__ __launch_bounds__(256) void convert_w_t(
    const float* __restrict__ W, __nv_bfloat16* __restrict__ whi,
    __nv_bfloat16* __restrict__ wlo)
{
    __shared__ float ts[32][33];
    int n0 = blockIdx.x * 32, k0 = blockIdx.y * 32;
    int lx = threadIdx.x & 31, ly = threadIdx.x >> 5;
#pragma unroll
    for (int i = 0; i < 4; i++) {
        int r = ly + i * 8;
        ts[r][lx] = W[(size_t)(k0 + r) * D_ + n0 + lx];
    }
    __syncthreads();
#pragma unroll
    for (int i = 0; i < 4; i++) {
        int ln = ly + i * 8;
        float v = ts[lx][ln];
        __nv_bfloat16 h = __float2bfloat16(v);
        whi[(size_t)(n0 + ln) * D_ + k0 + lx] = h;
        wlo[(size_t)(n0 + ln) * D_ + k0 + lx] = __float2bfloat16(v - __bfloat162float(h));
    }
}

// ---------------------------------------------------------------------------
// Mask tile flags: one CTA per 128x128 tile; flag=1 iff all-true.
// ---------------------------------------------------------------------------
__global__ __launch_bounds__(256) void mask_flags(
    const unsigned char* __restrict__ m8, int* __restrict__ flags)
{
    const int lt = blockIdx.x >> 4, st = blockIdx.x & 15;
    const bool maskInt = (m8[0] != 0 && m8[1] == 0 && m8[2] == 0 && m8[3] == 0);
    bool all = true;
    if (maskInt) {
        const int* m32 = reinterpret_cast<const int*>(m8);
#pragma unroll
        for (int i = 0; i < 16; i++) {
            int e = threadIdx.x + i * 256;
            int r = e >> 5, c4 = e & 31;
            int4 v = reinterpret_cast<const int4*>(
                m32 + (size_t)(lt * 128 + r) * S_ + st * 128)[c4];
            all = all && v.x && v.y && v.z && v.w;
        }
    } else {
#pragma unroll
        for (int i = 0; i < 4; i++) {
            int e = threadIdx.x + i * 256;
            int r = e >> 3, c = e & 7;
            uint4 v = reinterpret_cast<const uint4*>(
                m8 + (size_t)(lt * 128 + r) * S_ + st * 128)[c];
            uint32_t z = ((v.x - 0x01010101u) & ~v.x & 0x80808080u)
                       | ((v.y - 0x01010101u) & ~v.y & 0x80808080u)
                       | ((v.z - 0x01010101u) & ~v.z & 0x80808080u)
                       | ((v.w - 0x01010101u) & ~v.w & 0x80808080u);
            all = all && (z == 0u);
        }
    }
    all = __syncthreads_and(all) != 0;
    if (threadIdx.x == 0) flags[blockIdx.x] = all ? 1 : 0;
}

// ---------------------------------------------------------------------------
// bf16x3 projection GEMM on mma.sync: C[4096 x 1024] = X @ W + bias
// headLayout=1: write hi/lo bf16 to [B,H,T,DK]; else fp32 row-major.
// ---------------------------------------------------------------------------
#define PITCH 80
#define TILE_B (128 * PITCH)
#define OFF_AHI 0
#define OFF_ALO (TILE_B)
#define OFF_BHI (2 * TILE_B)
#define OFF_BLO (3 * TILE_B)
#define STAGE_B (4 * TILE_B)
#define PROJ_SMEM (2 * STAGE_B)
#define NKT (D_ / 32)

__global__ __launch_bounds__(256) void proj_mma_kernel(
    const __nv_bfloat16* __restrict__ Xhi, const __nv_bfloat16* __restrict__ Xlo,
    const __nv_bfloat16* __restrict__ Whi, const __nv_bfloat16* __restrict__ Wlo,
    const float* __restrict__ bias, float* __restrict__ outf,
    __nv_bfloat16* __restrict__ outhi, __nv_bfloat16* __restrict__ outlo,
    int headLayout)
{
    extern __shared__ char smem[];
    const uint32_t sb = smem_u32(smem);
    const int tid = threadIdx.x, wid = tid >> 5, lane = tid & 31;
    const int wm = wid >> 2, wn = wid & 3;
    const int m0 = blockIdx.y * 128, n0 = blockIdx.x * 128;

    const uint4* gXhi = reinterpret_cast<const uint4*>(Xhi);
    const uint4* gXlo = reinterpret_cast<const uint4*>(Xlo);
    const uint4* gWhi = reinterpret_cast<const uint4*>(Whi);
    const uint4* gWlo = reinterpret_cast<const uint4*>(Wlo);

    float acc[4][4][4];
#pragma unroll
    for (int i = 0; i < 4; i++)
#pragma unroll
        for (int j = 0; j < 4; j++)
#pragma unroll
            for (int r = 0; r < 4; r++) acc[i][j][r] = 0.0f;

    const int ldr0 = tid >> 2, ldc = tid & 3;
    {
#pragma unroll
        for (int i = 0; i < 2; i++) {
            int r = ldr0 + i * 64;
            size_t ga = (size_t)(m0 + r) * (D_ / 8) + ldc;
            size_t gb = (size_t)(n0 + r) * (D_ / 8) + ldc;
            uint32_t off = (uint32_t)(r * PITCH + ldc * 16);
            *reinterpret_cast<uint4*>(smem + OFF_AHI + off) = gXhi[ga];
            *reinterpret_cast<uint4*>(smem + OFF_ALO + off) = gXlo[ga];
            *reinterpret_cast<uint4*>(smem + OFF_BHI + off) = gWhi[gb];
            *reinterpret_cast<uint4*>(smem + OFF_BLO + off) = gWlo[gb];
        }
    }
    __syncthreads();

    const int lrow = lane & 15;
    const int lkb  = (lane >> 4) * 16;

    for (int kt = 0; kt < NKT; kt++) {
        const int buf = kt & 1;
        const bool pre = (kt + 1 < NKT);
        uint4 st[8];
        if (pre) {
            const int kq = (kt + 1) * 4;
#pragma unroll
            for (int i = 0; i < 2; i++) {
                int r = ldr0 + i * 64;
                size_t ga = (size_t)(m0 + r) * (D_ / 8) + kq + ldc;
                size_t gb = (size_t)(n0 + r) * (D_ / 8) + kq + ldc;
                st[i]     = gXhi[ga];
                st[2 + i] = gXlo[ga];
                st[4 + i] = gWhi[gb];
                st[6 + i] = gWlo[gb];
            }
        }
        const uint32_t sbase = sb + buf * STAGE_B;
#pragma unroll
        for (int k16 = 0; k16 < 2; k16++) {
            const uint32_t kOff = k16 * 32 + lkb;
            uint32_t ahi[4][4], alo[4][4], bhi[2][4], blo[2][4];
#pragma unroll
            for (int im = 0; im < 4; im++) {
                uint32_t row = wm * 64 + im * 16 + lrow;
                uint32_t ad = sbase + row * PITCH + kOff;
                ldsm4(ahi[im][0], ahi[im][1], ahi[im][2], ahi[im][3], ad + OFF_AHI);
                ldsm4(alo[im][0], alo[im][1], alo[im][2], alo[im][3], ad + OFF_ALO);
            }
#pragma unroll
            for (int is = 0; is < 2; is++) {
                uint32_t nrow = wn * 32 + is * 16 + lrow;
                uint32_t bd = sbase + nrow * PITCH + kOff;
                ldsm4(bhi[is][0], bhi[is][1], bhi[is][2], bhi[is][3], bd + OFF_BHI);
                ldsm4(blo[is][0], blo[is][1], blo[is][2], blo[is][3], bd + OFF_BLO);
            }
#pragma unroll
            for (int im = 0; im < 4; im++)
#pragma unroll
                for (int is = 0; is < 2; is++)
#pragma unroll
                    for (int nn = 0; nn < 2; nn++) {
                        float* c = acc[im][is * 2 + nn];
                        mma16816(c, ahi[im], bhi[is][nn], bhi[is][nn + 2]);
                        mma16816(c, ahi[im], blo[is][nn], blo[is][nn + 2]);
                        mma16816(c, alo[im], bhi[is][nn], bhi[is][nn + 2]);
                    }
        }
        if (pre) {
            char* dst = smem + ((kt + 1) & 1) * STAGE_B;
#pragma unroll
            for (int i = 0; i < 2; i++) {
                int r = ldr0 + i * 64;
                uint32_t off = (uint32_t)(r * PITCH + ldc * 16);
                *reinterpret_cast<uint4*>(dst + OFF_AHI + off) = st[i];
                *reinterpret_cast<uint4*>(dst + OFF_ALO + off) = st[2 + i];
                *reinterpret_cast<uint4*>(dst + OFF_BHI + off) = st[4 + i];
                *reinterpret_cast<uint4*>(dst + OFF_BLO + off) = st[6 + i];
            }
        }
        __syncthreads();
    }

    // ---- epilogue ----
    const int qr = lane >> 2, qc = lane & 3;
#pragma unroll
    for (int im = 0; im < 4; im++) {
#pragma unroll
        for (int in = 0; in < 4; in++) {
            int col = n0 + wn * 32 + in * 8 + qc * 2;
            float bx = bias[col], by = bias[col + 1];
#pragma unroll
            for (int half = 0; half < 2; half++) {
                int row = m0 + wm * 64 + im * 16 + qr + half * 8;
                float vx = acc[im][in][half * 2 + 0] + bx;
                float vy = acc[im][in][half * 2 + 1] + by;
                if (headLayout) {
                    int bI = row >> 11, tI = row & 2047;
                    int h = col >> 6, cc = col & 63;
                    size_t base = (((size_t)(bI * H_ + h) * L_ + tI) << 6) + cc;
                    __nv_bfloat16 hx = __float2bfloat16(vx);
                    __nv_bfloat16 hy = __float2bfloat16(vy);
                    *reinterpret_cast<__nv_bfloat162*>(outhi + base) =
                        __nv_bfloat162(hx, hy);
                    *reinterpret_cast<__nv_bfloat162*>(outlo + base) =
                        __nv_bfloat162(__float2bfloat16(vx - __bfloat162float(hx)),
                                       __float2bfloat16(vy - __bfloat162float(hy)));
                } else {
                    float2 v = make_float2(vx, vy);
                    *reinterpret_cast<float2*>(outf + (size_t)row * D_ + col) = v;
                }
            }
        }
    }
}

// ---------------------------------------------------------------------------
// Tensor-core flash attention + full attn-matrix output.
// CTA: 128 q rows x one (b,h). 8 warps, each 16 rows. s-tiles of 128 (16).
// Smem pitch 144 B (multiple of 16 for ldmatrix/cp.async; 16-byte row
// rotation mod 128 keeps ldmatrix conflict-free).
// ---------------------------------------------------------------------------
#define AP 144
#define A_TILE (128 * AP)           // 18432
#define A_QHI 0
#define A_QLO (A_TILE)              // 18432
#define A_ST0 (2 * A_TILE)          // 36864
#define A_STG (4 * A_TILE)          // 73728 per-stage stride
#define A_KHI 0
#define A_KLO (A_TILE)
#define A_VHI (2 * A_TILE)
#define A_VLO (3 * A_TILE)
#define A_MT   (A_ST0 + 2 * A_STG)  // 184320: m_tile [128][16] f32
#define A_INV  (A_MT + 8192)        // 192512
#define A_MFIN (A_INV + 512)        // 193024
#define A_SMEM (A_MFIN + 512)       // 193536

__global__ __launch_bounds__(256, 1) void attn_tc_kernel(
    const __nv_bfloat16* __restrict__ qhi_g, const __nv_bfloat16* __restrict__ qlo_g,
    const __nv_bfloat16* __restrict__ khi_g, const __nv_bfloat16* __restrict__ klo_g,
    const __nv_bfloat16* __restrict__ vhi_g, const __nv_bfloat16* __restrict__ vlo_g,
    const unsigned char* __restrict__ mask8, const int* __restrict__ maskflag,
    float* __restrict__ attn,
    __nv_bfloat16* __restrict__ ohi_g, __nv_bfloat16* __restrict__ olo_g)
{
    extern __shared__ char smem[];
    const uint32_t sb = smem_u32(smem);
    const int tid = threadIdx.x, w = tid >> 5, lane = tid & 31;
    const int b = blockIdx.z, h = blockIdx.y;
    const int ltile = blockIdx.x, l0 = ltile * 128;
    const float scale = 0.125f;

    const size_t bhOff = (size_t)(b * H_ + h) * S_ * DK_;
    float* ap = attn + ((size_t)(b * H_ + h) * L_ + l0) * S_;

    const bool maskInt = (mask8[0] != 0 && mask8[1] == 0 && mask8[2] == 0 && mask8[3] == 0);
    const int* mask32 = reinterpret_cast<const int*>(mask8);

    // ---- prologue: async-load Q tile + K/V stage 0 ----
    {
        const size_t qb = (size_t)(b * H_ + h) * L_ * DK_ + (size_t)l0 * DK_;
#pragma unroll
        for (int i = 0; i < 4; i++) {
            int cid = tid + i * 256;            // 1024 chunks per matrix
            int r = cid >> 3, c = cid & 7;
            cp16(sb + A_QHI + r * AP + c * 16, qhi_g + qb + r * DK_ + c * 8);
            cp16(sb + A_QLO + r * AP + c * 16, qlo_g + qb + r * DK_ + c * 8);
        }
#pragma unroll
        for (int i = 0; i < 4; i++) {
            int cid = tid + i * 256;
            int r = cid >> 3, c = cid & 7;
            size_t gs = bhOff + (size_t)r * DK_ + c * 8;
            uint32_t so = sb + A_ST0 + r * AP + c * 16;
            cp16(so + A_KHI, khi_g + gs);
            cp16(so + A_KLO, klo_g + gs);
            cp16(so + A_VHI, vhi_g + gs);
            cp16(so + A_VLO, vlo_g + gs);
        }
        CP_COMMIT();
    }

    // fragment lane decomposition
    const int lane15 = lane & 15;
    const int lkb = (lane >> 4) * 16;
    const int r4 = lane >> 2, c4 = lane & 3;
    const int row0 = 16 * w + r4;               // fragment rows row0, row0+8

    float oacc[8][4];
#pragma unroll
    for (int t = 0; t < 8; t++)
#pragma unroll
        for (int e = 0; e < 4; e++) oacc[t][e] = 0.0f;
    float mrun0 = -3.0e38f, mrun1 = -3.0e38f, srun0 = 0.0f, srun1 = 0.0f;

    const uint32_t qHiA = sb + A_QHI + (16 * w + lane15) * AP + lkb;
    const uint32_t qLoA = sb + A_QLO + (16 * w + lane15) * AP + lkb;

    float* mt = reinterpret_cast<float*>(smem + A_MT);

    for (int st = 0; st < 16; st++) {
        // prefetch next stage
        if (st + 1 < 16) {
            const int s0n = (st + 1) * 128;
            uint32_t stB = sb + A_ST0 + ((st + 1) & 1) * A_STG;
#pragma unroll
            for (int i = 0; i < 4; i++) {
                int cid = tid + i * 256;
                int r = cid >> 3, c = cid & 7;
                size_t gs = bhOff + (size_t)(s0n + r) * DK_ + c * 8;
                uint32_t so = stB + r * AP + c * 16;
                cp16(so + A_KHI, khi_g + gs);
                cp16(so + A_KLO, klo_g + gs);
                cp16(so + A_VHI, vhi_g + gs);
                cp16(so + A_VLO, vlo_g + gs);
            }
            CP_COMMIT();
            CP_WAIT(1);
        } else {
            CP_WAIT(0);
        }
        __syncthreads();

        const int s0 = st * 128;
        const uint32_t stB = sb + A_ST0 + (st & 1) * A_STG;

        // ---- S = Q K^T (bf16x3) ----
        float sacc[16][4];
#pragma unroll
        for (int t = 0; t < 16; t++)
#pragma unroll
            for (int e = 0; e < 4; e++) sacc[t][e] = 0.0f;

#pragma unroll
        for (int k16 = 0; k16 < 4; k16++) {
            uint32_t aqh[4], aql[4];
            ldsm4(aqh[0], aqh[1], aqh[2], aqh[3], qHiA + k16 * 32);
            ldsm4(aql[0], aql[1], aql[2], aql[3], qLoA + k16 * 32);
#pragma unroll
            for (int ns = 0; ns < 8; ns++) {
                uint32_t bh[4], bl[4];
                uint32_t kd = stB + (16 * ns + lane15) * AP + lkb + k16 * 32;
                ldsm4(bh[0], bh[1], bh[2], bh[3], kd + A_KHI);
                ldsm4(bl[0], bl[1], bl[2], bl[3], kd + A_KLO);
#pragma unroll
                for (int nn = 0; nn < 2; nn++) {
                    float* c = sacc[ns * 2 + nn];
                    mma16816(c, aqh, bh[nn], bh[nn + 2]);
                    mma16816(c, aqh, bl[nn], bl[nn + 2]);
                    mma16816(c, aql, bh[nn], bh[nn + 2]);
                }
            }
        }

        // ---- scale + mask ----
        const int flag = maskflag[ltile * 16 + st];
        if (flag) {
#pragma unroll
            for (int t = 0; t < 16; t++)
#pragma unroll
                for (int e = 0; e < 4; e++) sacc[t][e] *= scale;
        } else {
#pragma unroll
            for (int t = 0; t < 16; t++) {
                int col = s0 + 8 * t + 2 * c4;
#pragma unroll
                for (int e = 0; e < 4; e++) {
                    int l = l0 + row0 + (e >> 1) * 8;
                    int cc = col + (e & 1);
                    bool keep = maskInt ? (mask32[(size_t)l * S_ + cc] != 0)
                                        : (mask8[(size_t)l * S_ + cc] != 0);
                    sacc[t][e] = keep ? sacc[t][e] * scale : -1.0e30f;
                }
            }
        }

        // ---- row max (tile) ----
        float m0 = -3.0e38f, m1 = -3.0e38f;
#pragma unroll
        for (int t = 0; t < 16; t++) {
            m0 = fmaxf(m0, fmaxf(sacc[t][0], sacc[t][1]));
            m1 = fmaxf(m1, fmaxf(sacc[t][2], sacc[t][3]));
        }
        m0 = fmaxf(m0, __shfl_xor_sync(0xffffffff, m0, 1));
        m0 = fmaxf(m0, __shfl_xor_sync(0xffffffff, m0, 2));
        m1 = fmaxf(m1, __shfl_xor_sync(0xffffffff, m1, 1));
        m1 = fmaxf(m1, __shfl_xor_sync(0xffffffff, m1, 2));

        float nm0 = fmaxf(mrun0, m0), nm1 = fmaxf(mrun1, m1);
        float al0 = fexp(mrun0 - nm0), al1 = fexp(mrun1 - nm1);
        mrun0 = nm0; mrun1 = nm1;
        srun0 *= al0; srun1 *= al1;
#pragma unroll
        for (int t = 0; t < 8; t++) {
            oacc[t][0] *= al0; oacc[t][1] *= al0;
            oacc[t][2] *= al1; oacc[t][3] *= al1;
        }

        // ---- exp (in place), row-sum partials, store p~ to global ----
#pragma unroll
        for (int t = 0; t < 16; t++) {
            sacc[t][0] = fexp(sacc[t][0] - nm0);
            sacc[t][1] = fexp(sacc[t][1] - nm0);
            sacc[t][2] = fexp(sacc[t][2] - nm1);
            sacc[t][3] = fexp(sacc[t][3] - nm1);
            srun0 += sacc[t][0] + sacc[t][1];
            srun1 += sacc[t][2] + sacc[t][3];
            int col = s0 + 8 * t + 2 * c4;
            *reinterpret_cast<float2*>(ap + (size_t)row0 * S_ + col) =
                make_float2(sacc[t][0], sacc[t][1]);
            *reinterpret_cast<float2*>(ap + (size_t)(row0 + 8) * S_ + col) =
                make_float2(sacc[t][2], sacc[t][3]);
        }
        if (c4 == 0) {
            mt[row0 * 16 + st] = nm0;
            mt[(row0 + 8) * 16 + st] = nm1;
        }

        // ---- O += P V (bf16x3, P split on the fly) ----
#pragma unroll
        for (int kp = 0; kp < 8; kp++) {
            const float* pa = sacc[2 * kp];
            const float* pb = sacc[2 * kp + 1];
            float h00 = __bfloat162float(__float2bfloat16(pa[0]));
            float h01 = __bfloat162float(__float2bfloat16(pa[1]));
            float h02 = __bfloat162float(__float2bfloat16(pa[2]));
            float h03 = __bfloat162float(__float2bfloat16(pa[3]));
            float h10 = __bfloat162float(__float2bfloat16(pb[0]));
            float h11 = __bfloat162float(__float2bfloat16(pb[1]));
            float h12 = __bfloat162float(__float2bfloat16(pb[2]));
            float h13 = __bfloat162float(__float2bfloat16(pb[3]));
            uint32_t phi[4], plo[4];
            phi[0] = pack_bf2(h00, h01); phi[1] = pack_bf2(h02, h03);
            phi[2] = pack_bf2(h10, h11); phi[3] = pack_bf2(h12, h13);
            plo[0] = pack_bf2(pa[0] - h00, pa[1] - h01);
            plo[1] = pack_bf2(pa[2] - h02, pa[3] - h03);
            plo[2] = pack_bf2(pb[0] - h10, pb[1] - h11);
            plo[3] = pack_bf2(pb[2] - h12, pb[3] - h13);
#pragma unroll
            for (int nd = 0; nd < 4; nd++) {
                uint32_t vd = stB + (16 * kp + lane15) * AP + nd * 32 + lkb;
                uint32_t vh[4], vl[4];
                ldsm4t(vh[0], vh[1], vh[2], vh[3], vd + A_VHI);
                ldsm4t(vl[0], vl[1], vl[2], vl[3], vd + A_VLO);
                float* c0 = oacc[nd * 2];
                float* c1 = oacc[nd * 2 + 1];
                mma16816(c0, phi, vh[0], vh[1]);
                mma16816(c0, plo, vh[0], vh[1]);
                mma16816(c0, phi, vl[0], vl[1]);
                mma16816(c1, phi, vh[2], vh[3]);
                mma16816(c1, plo, vh[2], vh[3]);
                mma16816(c1, phi, vl[2], vl[3]);
            }
        }
        __syncthreads();
    }

    // ---- finalize row stats ----
    srun0 += __shfl_xor_sync(0xffffffff, srun0, 1);
    srun0 += __shfl_xor_sync(0xffffffff, srun0, 2);
    srun1 += __shfl_xor_sync(0xffffffff, srun1, 1);
    srun1 += __shfl_xor_sync(0xffffffff, srun1, 2);
    float inv0 = 1.0f / srun0, inv1 = 1.0f / srun1;

    float* invs = reinterpret_cast<float*>(smem + A_INV);
    float* mfin = reinterpret_cast<float*>(smem + A_MFIN);
    if (c4 == 0) {
        invs[row0] = inv0; mfin[row0] = mrun0;
        invs[row0 + 8] = inv1; mfin[row0 + 8] = mrun1;
    }

    // ---- O epilogue: write hi/lo bf16 A-operand for final projection ----
    {
        const int rG0 = b * L_ + l0 + row0;
#pragma unroll
        for (int t = 0; t < 8; t++) {
            int d = 8 * t + 2 * c4;
            float v0 = oacc[t][0] * inv0, v1 = oacc[t][1] * inv0;
            float v2 = oacc[t][2] * inv1, v3 = oacc[t][3] * inv1;
            size_t a0 = (size_t)rG0 * D_ + h * DK_ + d;
            size_t a1 = (size_t)(rG0 + 8) * D_ + h * DK_ + d;
            __nv_bfloat16 h0 = __float2bfloat16(v0), h1 = __float2bfloat16(v1);
            __nv_bfloat16 h2 = __float2bfloat16(v2), h3 = __float2bfloat16(v3);
            *reinterpret_cast<__nv_bfloat162*>(ohi_g + a0) = __nv_bfloat162(h0, h1);
            *reinterpret_cast<__nv_bfloat162*>(ohi_g + a1) = __nv_bfloat162(h2, h3);
            *reinterpret_cast<__nv_bfloat162*>(olo_g + a0) =
                __nv_bfloat162(__float2bfloat16(v0 - __bfloat162float(h0)),
                               __float2bfloat16(v1 - __bfloat162float(h1)));
            *reinterpret_cast<__nv_bfloat162*>(olo_g + a1) =
                __nv_bfloat162(__float2bfloat16(v2 - __bfloat162float(h2)),
                               __float2bfloat16(v3 - __bfloat162float(h3)));
        }
    }
    __syncthreads();

    // ---- scale table: mt[row][st] -> exp(m_tile - m_final) * inv ----
#pragma unroll
    for (int i = 0; i < 8; i++) {
        int e = tid + i * 256;              // 2048 entries
        int row = e >> 4;
        mt[e] = fexp(mt[e] - mfin[row]) * invs[row];
    }
    __syncthreads();

    // ---- phase 2: rescale attn tile in global (coalesced float4) ----
#pragma unroll 4
    for (int i = 0; i < 256; i++) {
        int idx = tid + i * 256;            // 65536 float4
        int row = idx >> 9, f4 = idx & 511;
        int st = f4 >> 5;
        float sc = mt[row * 16 + st];
        float4* p = reinterpret_cast<float4*>(ap + (size_t)row * S_) + f4;
        float4 v = *p;
        v.x *= sc; v.y *= sc; v.z *= sc; v.w *= sc;
        *p = v;
    }
}

// ---------------------------------------------------------------------------
// kernel_launch
// ---------------------------------------------------------------------------
extern "C" void kernel_launch(void* const* d_in, const int* in_sizes, int n_in,
                              void* d_out, int out_size)
{
    const float* queries = (const float*)d_in[0];
    const float* keys    = (const float*)d_in[1];
    const float* values  = (const float*)d_in[2];
    const unsigned char* mask = (const unsigned char*)d_in[3];
    const float* Wq = (const float*)d_in[4];
    const float* bq = (const float*)d_in[5];
    const float* Wk = (const float*)d_in[6];
    const float* bk = (const float*)d_in[7];
    const float* Wv = (const float*)d_in[8];
    const float* bv = (const float*)d_in[9];
    const float* Wo = (const float*)d_in[10];
    const float* bo = (const float*)d_in[11];

    float* out = (float*)d_out;
    const size_t OUT_ELEMS  = (size_t)B_ * L_ * D_;
    const size_t ATTN_ELEMS = (size_t)B_ * H_ * L_ * S_;

    float *pattn_scratch;
    __nv_bfloat16 *pqhi, *pqlo, *pkhi, *pklo, *pvhi, *pvlo, *pxhi, *pxlo, *pwhi, *pwlo;
    int* pflags;
    cudaGetSymbolAddress((void**)&pattn_scratch, g_attn_scratch);
    cudaGetSymbolAddress((void**)&pqhi, g_qhi);
    cudaGetSymbolAddress((void**)&pqlo, g_qlo);
    cudaGetSymbolAddress((void**)&pkhi, g_khi);
    cudaGetSymbolAddress((void**)&pklo, g_klo);
    cudaGetSymbolAddress((void**)&pvhi, g_vhi);
    cudaGetSymbolAddress((void**)&pvlo, g_vlo);
    cudaGetSymbolAddress((void**)&pxhi, g_xhi);
    cudaGetSymbolAddress((void**)&pxlo, g_xlo);
    cudaGetSymbolAddress((void**)&pwhi, g_whi);
    cudaGetSymbolAddress((void**)&pwlo, g_wlo);
    cudaGetSymbolAddress((void**)&pflags, g_maskflag);

    float* attn = ((size_t)out_size >= OUT_ELEMS + ATTN_ELEMS)
                      ? (out + OUT_ELEMS) : pattn_scratch;

    static int attrSet = 0;
    if (!attrSet) {
        cudaFuncSetAttribute(proj_mma_kernel,
                             cudaFuncAttributeMaxDynamicSharedMemorySize, PROJ_SMEM);
        cudaFuncSetAttribute(attn_tc_kernel,
                             cudaFuncAttributeMaxDynamicSharedMemorySize, A_SMEM);
        attrSet = 1;
    }

    const int n4 = NROW * D_ / 4;
    const dim3 gproj(D_ / 128, NROW / 128);   // (8, 32)
    const dim3 gw(D_ / 32, D_ / 32);          // (32, 32)

    // Q projection -> qhi/qlo [B,H,L,DK]
    convert_hilo<<<n4 / 256, 256>>>((const float4*)queries, pxhi, pxlo, n4);
    convert_w_t<<<gw, 256>>>(Wq, pwhi, pwlo);
    proj_mma_kernel<<<gproj, 256, PROJ_SMEM>>>(pxhi, pxlo, pwhi, pwlo, bq,
                                               nullptr, pqhi, pqlo, 1);
    // K projection
    convert_hilo<<<n4 / 256, 256>>>((const float4*)keys, pxhi, pxlo, n4);
    convert_w_t<<<gw, 256>>>(Wk, pwhi, pwlo);
    proj_mma_kernel<<<gproj, 256, PROJ_SMEM>>>(pxhi, pxlo, pwhi, pwlo, bk,
                                               nullptr, pkhi, pklo, 1);
    // V projection
    convert_hilo<<<n4 / 256, 256>>>((const float4*)values, pxhi, pxlo, n4);
    convert_w_t<<<gw, 256>>>(Wv, pwhi, pwlo);
    proj_mma_kernel<<<gproj, 256, PROJ_SMEM>>>(pxhi, pxlo, pwhi, pwlo, bv,
                                               nullptr, pvhi, pvlo, 1);

    // mask tile flags
    mask_flags<<<256, 256>>>(mask, pflags);

    // attention (writes attn matrix + head outputs hi/lo into g_xhi/g_xlo)
    dim3 ga(L_ / 128, H_, B_);                // (16, 16, 2)
    attn_tc_kernel<<<ga, 256, A_SMEM>>>(pqhi, pqlo, pkhi, pklo, pvhi, pvlo,
                                        mask, pflags, attn, pxhi, pxlo);

    // output projection (A = attn head outputs already hi/lo in g_xhi/g_xlo)
    convert_w_t<<<gw, 256>>>(Wo, pwhi, pwlo);
    proj_mma_kernel<<<gproj, 256, PROJ_SMEM>>>(pxhi, pxlo, pwhi, pwlo, bo,
                                               out, nullptr, nullptr, 0);
}